// round 15
// baseline (speedup 1.0000x reference)
#include <cuda_runtime.h>
#include <cuda_bf16.h>
#include <cstdint>

#define HIDDEN   7168
#define NEXPERTS 256
#define TOPK     8
#define NGROUP   8
#define TOPKGRP  4
#define SCALING  2.5f

#define MAX_T    8192
#define KT       64
#define NKT      (HIDDEN / KT)      // 112
#define TERM_BYTES 16384            // 128 rows x 64 bf16 x 2B
#define RISKY_TH 8e-5f

// ---------------------------------------------------------------------------
// device scratch
// ---------------------------------------------------------------------------
__device__ float g_logits[MAX_T * NEXPERTS];
__device__ __align__(16) __nv_bfloat16 g_bterm[2][NEXPERTS * HIDDEN];
__device__ int g_risky_count;
__device__ int g_risky[MAX_T];

// ---------------------------------------------------------------------------
// helpers
// ---------------------------------------------------------------------------
__device__ __forceinline__ uint32_t smem_u32(const void* p) {
    uint32_t a;
    asm("{ .reg .u64 t; cvta.to.shared.u64 t, %1; cvt.u32.u64 %0, t; }"
        : "=r"(a) : "l"(p));
    return a;
}
__device__ __forceinline__ uint32_t sw128(uint32_t off) {
    return off ^ ((off >> 3) & 0x70);
}
#define STS128(a, r0, r1, r2, r3) \
    asm volatile("st.shared.v4.b32 [%0], {%1,%2,%3,%4};" :: "r"(a), "r"(r0), "r"(r1), "r"(r2), "r"(r3) : "memory")
#define CP_ASYNC16(dst, src) \
    asm volatile("cp.async.ca.shared.global [%0], [%1], 16;" :: "r"(dst), "l"(src) : "memory")
#define CP_COMMIT() asm volatile("cp.async.commit_group;" ::: "memory")
#define CP_WAIT1()  asm volatile("cp.async.wait_group 1;" ::: "memory")
#define CP_WAIT0()  asm volatile("cp.async.wait_group 0;" ::: "memory")

__device__ __forceinline__ void ldsm4(uint32_t* r, uint32_t addr) {
    asm volatile("ldmatrix.sync.aligned.m8n8.x4.shared.b16 {%0,%1,%2,%3}, [%4];"
        : "=r"(r[0]), "=r"(r[1]), "=r"(r[2]), "=r"(r[3]) : "r"(addr));
}
__device__ __forceinline__ void mma_bf16(float* c, const uint32_t* a,
                                         uint32_t b0, uint32_t b1) {
    asm volatile(
        "mma.sync.aligned.m16n8k16.row.col.f32.bf16.bf16.f32 "
        "{%0,%1,%2,%3}, {%4,%5,%6,%7}, {%8,%9}, {%0,%1,%2,%3};"
        : "+f"(c[0]), "+f"(c[1]), "+f"(c[2]), "+f"(c[3])
        : "r"(a[0]), "r"(a[1]), "r"(a[2]), "r"(a[3]), "r"(b0), "r"(b1));
}

// ---------------------------------------------------------------------------
// fp32 -> 2x bf16 split of 8 consecutive elements -> packed bf16x2 words
// residual after 2 terms is ~2^-17 relative; covered by margin rescue.
// ---------------------------------------------------------------------------
__device__ __forceinline__ uint32_t pk2(float lo, float hi) {
    uint32_t r;
    asm("cvt.rn.bf16x2.f32 %0, %1, %2;" : "=r"(r) : "f"(hi), "f"(lo));
    return r;
}
__device__ __forceinline__ void split8_2(const float* f, uint32_t* p0, uint32_t* p1) {
#pragma unroll
    for (int j = 0; j < 4; j++) {
        float a = f[2 * j], b = f[2 * j + 1];
        uint32_t c0 = pk2(a, b);
        float a0 = __uint_as_float(c0 << 16);
        float b0 = __uint_as_float(c0 & 0xffff0000u);
        uint32_t c1 = pk2(a - a0, b - b0);
        p0[j] = c0; p1[j] = c1;
    }
}

// ---------------------------------------------------------------------------
// small utility kernels
// ---------------------------------------------------------------------------
__global__ void reset_kernel() {
    if (threadIdx.x == 0) g_risky_count = 0;
}

__global__ void __launch_bounds__(256)
presplit_kernel(const float* __restrict__ W) {
    size_t i = ((size_t)blockIdx.x * 256 + threadIdx.x) * 8;
    const float4* s = reinterpret_cast<const float4*>(W + i);
    float4 f0 = s[0], f1 = s[1];
    float f[8] = {f0.x, f0.y, f0.z, f0.w, f1.x, f1.y, f1.z, f1.w};
    uint32_t p0[4], p1[4];
    split8_2(f, p0, p1);
    *reinterpret_cast<uint4*>(&g_bterm[0][i]) = make_uint4(p0[0], p0[1], p0[2], p0[3]);
    *reinterpret_cast<uint4*>(&g_bterm[1][i]) = make_uint4(p1[0], p1[1], p1[2], p1[3]);
}

// ---------------------------------------------------------------------------
// GEMM: logits = x @ W^T, 4-product 2-term bf16 emulation on mma.sync.
// grid (T/128, 2), 256 threads (8 warps of 32x64), 128KB dynamic smem.
// ---------------------------------------------------------------------------
#define SMEM_A(buf, t) ((uint32_t)((buf) * 2 + (t)) * TERM_BYTES)
#define SMEM_B(buf, t) ((uint32_t)(65536 + ((buf) * 2 + (t)) * TERM_BYTES))
#define SMEM_TOTAL     131072

__global__ void __launch_bounds__(256, 1)
gemm_tc_kernel(const float* __restrict__ A, int T) {
    extern __shared__ char smem[];
    const uint32_t sb = smem_u32(smem);
    const int tid = threadIdx.x, wid = tid >> 5, lane = tid & 31;
    const int rowBase = blockIdx.x * 128;
    const int colBase = blockIdx.y * 128;
    const int warpM = (wid & 3) * 32;
    const int warpN = (wid >> 2) * 64;

    const float* Abase = A + (size_t)rowBase * HIDDEN;

    const int ldRow[4] = {(tid + 0) >> 3, (tid + 256) >> 3,
                          (tid + 512) >> 3, (tid + 768) >> 3};
    const int ldKc = (tid & 7) * 8;

    float acc[2][8][4];
#pragma unroll
    for (int mt = 0; mt < 2; mt++)
#pragma unroll
        for (int nf = 0; nf < 8; nf++)
#pragma unroll
            for (int j = 0; j < 4; j++) acc[mt][nf][j] = 0.0f;

    // ---- prologue: A(0) regs + B(0) cp.async ----
    float4 aReg[8];
#pragma unroll
    for (int i = 0; i < 4; i++) {
        const float* src = Abase + (size_t)ldRow[i] * HIDDEN + ldKc;
        aReg[2 * i]     = *reinterpret_cast<const float4*>(src);
        aReg[2 * i + 1] = *reinterpret_cast<const float4*>(src + 4);
    }
#pragma unroll
    for (int t = 0; t < 2; t++)
#pragma unroll
        for (int i = 0; i < 4; i++) {
            const __nv_bfloat16* src =
                &g_bterm[t][(size_t)(colBase + ldRow[i]) * HIDDEN + ldKc];
            CP_ASYNC16(sb + SMEM_B(0, t) + sw128((uint32_t)(ldRow[i] * 128 + ldKc * 2)),
                       src);
        }
    CP_COMMIT();

    for (int kt = 0; kt < NKT; kt++) {
        const int buf = kt & 1;

        __syncthreads();  // previous compute done; buffers free

        // ---- STS A(kt): split fp32 regs into 2 bf16 term tiles ----
#pragma unroll
        for (int i = 0; i < 4; i++) {
            float f[8] = {aReg[2 * i].x, aReg[2 * i].y, aReg[2 * i].z, aReg[2 * i].w,
                          aReg[2 * i + 1].x, aReg[2 * i + 1].y,
                          aReg[2 * i + 1].z, aReg[2 * i + 1].w};
            uint32_t p0[4], p1[4];
            split8_2(f, p0, p1);
            const uint32_t sw = sw128((uint32_t)(ldRow[i] * 128 + ldKc * 2));
            STS128(sb + SMEM_A(buf, 0) + sw, p0[0], p0[1], p0[2], p0[3]);
            STS128(sb + SMEM_A(buf, 1) + sw, p1[0], p1[1], p1[2], p1[3]);
        }

        // ---- prefetch tile kt+1 ----
        if (kt + 1 < NKT) {
            const int nbuf = buf ^ 1;
            const int koff = (kt + 1) * KT;
#pragma unroll
            for (int t = 0; t < 2; t++)
#pragma unroll
                for (int i = 0; i < 4; i++) {
                    const __nv_bfloat16* src =
                        &g_bterm[t][(size_t)(colBase + ldRow[i]) * HIDDEN + koff + ldKc];
                    CP_ASYNC16(sb + SMEM_B(nbuf, t) +
                                   sw128((uint32_t)(ldRow[i] * 128 + ldKc * 2)),
                               src);
                }
            CP_COMMIT();
#pragma unroll
            for (int i = 0; i < 4; i++) {
                const float* src = Abase + (size_t)ldRow[i] * HIDDEN + koff + ldKc;
                aReg[2 * i]     = *reinterpret_cast<const float4*>(src);
                aReg[2 * i + 1] = *reinterpret_cast<const float4*>(src + 4);
            }
            CP_WAIT1();  // B(kt) complete (B(kt+1) may stay pending)
        } else {
            CP_WAIT0();
        }
        __syncthreads();

        // ---- compute tile kt: 4 k-steps x 4 term-products ----
#pragma unroll
        for (int ks = 0; ks < 4; ks++) {
            const uint32_t colb = (uint32_t)(ks * 32 + (lane >> 4) * 16);

            uint32_t afr[2][2][4];
#pragma unroll
            for (int t = 0; t < 2; t++)
#pragma unroll
                for (int mt = 0; mt < 2; mt++) {
                    const uint32_t row = (uint32_t)(warpM + mt * 16 + (lane & 15));
                    ldsm4(afr[t][mt], sb + SMEM_A(buf, t) + sw128(row * 128 + colb));
                }

#pragma unroll
            for (int tb = 0; tb < 2; tb++) {
                uint32_t bfr[4][4];
#pragma unroll
                for (int nr = 0; nr < 4; nr++) {
                    const uint32_t row = (uint32_t)(warpN + nr * 16 + (lane & 15));
                    ldsm4(bfr[nr], sb + SMEM_B(buf, tb) + sw128(row * 128 + colb));
                }
#pragma unroll
                for (int ta = 0; ta < 2; ta++)
#pragma unroll
                    for (int mt = 0; mt < 2; mt++)
#pragma unroll
                        for (int nr = 0; nr < 4; nr++) {
                            mma_bf16(acc[mt][nr * 2],     afr[ta][mt], bfr[nr][0], bfr[nr][2]);
                            mma_bf16(acc[mt][nr * 2 + 1], afr[ta][mt], bfr[nr][1], bfr[nr][3]);
                        }
            }
        }
    }

    // ---- epilogue ----
#pragma unroll
    for (int mt = 0; mt < 2; mt++) {
        const int r0 = rowBase + warpM + mt * 16 + (lane >> 2);
#pragma unroll
        for (int nf = 0; nf < 8; nf++) {
            const int col = colBase + warpN + nf * 8 + (lane & 3) * 2;
            *reinterpret_cast<float2*>(g_logits + (size_t)r0 * NEXPERTS + col) =
                make_float2(acc[mt][nf][0], acc[mt][nf][1]);
            *reinterpret_cast<float2*>(g_logits + (size_t)(r0 + 8) * NEXPERTS + col) =
                make_float2(acc[mt][nf][2], acc[mt][nf][3]);
        }
    }
}

// ---------------------------------------------------------------------------
// warp-collective routing for one token; returns min decision margin.
// ---------------------------------------------------------------------------
__device__ __forceinline__ float route_token_warp(const float* lg, const float* bb,
                                                  int lane, int token, int T,
                                                  float* out) {
    const float NEG_INF = __int_as_float(0xff800000);

    float s[8], sc[8];
#pragma unroll
    for (int j = 0; j < 8; j++) {
        s[j]  = 1.0f / (1.0f + expf(-lg[j]));
        sc[j] = s[j] + bb[j];
    }

    // group top-2 sum (groups of 32 experts = 4 lanes)
    float m1 = NEG_INF, m2 = NEG_INF;
#pragma unroll
    for (int j = 0; j < 8; j++) {
        float v = sc[j];
        if (v > m1) { m2 = m1; m1 = v; }
        else if (v > m2) { m2 = v; }
    }
#pragma unroll
    for (int off = 1; off <= 2; off <<= 1) {
        float om1 = __shfl_xor_sync(0xffffffffu, m1, off);
        float om2 = __shfl_xor_sync(0xffffffffu, m2, off);
        float n1 = fmaxf(m1, om1);
        float n2 = fmaxf(fminf(m1, om1), fmaxf(m2, om2));
        m1 = n1; m2 = n2;
    }
    const float gscore = m1 + m2;

    float gs[8];
#pragma unroll
    for (int g = 0; g < 8; g++)
        gs[g] = __shfl_sync(0xffffffffu, gscore, g * 4);

    // group selection + margin (4th selected vs 5th)
    float val4 = 1e30f, val5 = -1e30f;
    int myrank = 0;
#pragma unroll
    for (int g = 0; g < 8; g++) {
        int rank = 0;
#pragma unroll
        for (int h = 0; h < 8; h++)
            rank += (gs[h] > gs[g]) || (gs[h] == gs[g] && h < g);
        if (rank < TOPKGRP) val4 = fminf(val4, gs[g]);
        else                val5 = fmaxf(val5, gs[g]);
        if (g == (lane >> 2)) myrank = rank;
    }
    float margin = val4 - val5;
    const bool sel = (myrank < TOPKGRP);

    float msc[8];
#pragma unroll
    for (int j = 0; j < 8; j++) msc[j] = sel ? sc[j] : 0.0f;

    // top-8 selection (+1 extra iteration for the 8-vs-9 margin)
    float wv[TOPK];
    int   wi[TOPK];
    float sum_s = 0.0f;
    float prev_bv = 0.0f;

#pragma unroll
    for (int it = 0; it <= TOPK; it++) {
        float bv = msc[0];
        int   bj = 0;
#pragma unroll
        for (int j = 1; j < 8; j++)
            if (msc[j] > bv) { bv = msc[j]; bj = j; }
        int   bidx = lane * 8 + bj;
        float bs   = s[bj];

#pragma unroll
        for (int off = 16; off >= 1; off >>= 1) {
            float ov = __shfl_xor_sync(0xffffffffu, bv, off);
            int   oi = __shfl_xor_sync(0xffffffffu, bidx, off);
            float os = __shfl_xor_sync(0xffffffffu, bs, off);
            if (ov > bv || (ov == bv && oi < bidx)) { bv = ov; bidx = oi; bs = os; }
        }
        if (it > 0) margin = fminf(margin, prev_bv - bv);
        prev_bv = bv;

        if (it < TOPK) {
            wv[it] = bs;
            wi[it] = bidx;
            sum_s += bs;
            if ((bidx >> 3) == lane) msc[bidx & 7] = NEG_INF;
        }
    }

    if (lane == 0) {
        const float inv = SCALING / (sum_s + 1e-20f);
        float* oidx = out + (size_t)token * TOPK;
        float* ow   = out + (size_t)T * TOPK + (size_t)token * TOPK;
#pragma unroll
        for (int it = 0; it < TOPK; it++) {
            oidx[it] = (float)wi[it];
            ow[it]   = wv[it] * inv;
        }
    }
    return margin;
}

// ---------------------------------------------------------------------------
// Routing: one warp per token; flags risky (small-margin) tokens.
// ---------------------------------------------------------------------------
__global__ void __launch_bounds__(256)
routing_kernel(const float* __restrict__ bias, float* __restrict__ out, int T) {
    const int warp = (blockIdx.x * blockDim.x + threadIdx.x) >> 5;
    const int lane = threadIdx.x & 31;
    if (warp >= T) return;

    const float* lrow = g_logits + (size_t)warp * NEXPERTS;
    float4 l0 = *reinterpret_cast<const float4*>(lrow + lane * 8);
    float4 l1 = *reinterpret_cast<const float4*>(lrow + lane * 8 + 4);
    float4 b0 = *reinterpret_cast<const float4*>(bias + lane * 8);
    float4 b1 = *reinterpret_cast<const float4*>(bias + lane * 8 + 4);
    float lg[8] = {l0.x, l0.y, l0.z, l0.w, l1.x, l1.y, l1.z, l1.w};
    float bb[8] = {b0.x, b0.y, b0.z, b0.w, b1.x, b1.y, b1.z, b1.w};

    float mm = route_token_warp(lg, bb, lane, warp, T, out);

    if (lane == 0 && mm < RISKY_TH) {
        int slot = atomicAdd(&g_risky_count, 1);
        g_risky[slot] = warp;
    }
}

// ---------------------------------------------------------------------------
// Exact fix: recompute risky tokens' logits with sequential fp32 FMA
// (R6's proven accumulation order) and redo routing.
// ---------------------------------------------------------------------------
#define FIX_TPB 4
#define FIX_SMEM ((FIX_TPB * HIDDEN + FIX_TPB * NEXPERTS) * 4)

__global__ void __launch_bounds__(256)
fix_kernel(const float* __restrict__ x, const float* __restrict__ w,
           const float* __restrict__ bias, float* __restrict__ out, int T) {
    const int cnt = g_risky_count;
    const int base = blockIdx.x * FIX_TPB;
    if (base >= cnt) return;
    const int ntok = min(FIX_TPB, cnt - base);

    extern __shared__ float fsm[];
    float* xs  = fsm;                      // [FIX_TPB][HIDDEN]
    float* lgs = fsm + FIX_TPB * HIDDEN;   // [FIX_TPB][NEXPERTS]

    for (int j = 0; j < ntok; j++) {
        const int tok = g_risky[base + j];
        const float4* src = reinterpret_cast<const float4*>(x + (size_t)tok * HIDDEN);
        float4* dst = reinterpret_cast<float4*>(xs + j * HIDDEN);
        for (int i = threadIdx.x; i < HIDDEN / 4; i += 256) dst[i] = src[i];
    }
    __syncthreads();

    const int e = threadIdx.x;
    const float4* wr = reinterpret_cast<const float4*>(w + (size_t)e * HIDDEN);
    float a0 = 0.0f, a1 = 0.0f, a2 = 0.0f, a3 = 0.0f;
    for (int k4 = 0; k4 < HIDDEN / 4; k4++) {
        const float4 wv = wr[k4];
        const int k = k4 * 4;
        a0 = fmaf(xs[0 * HIDDEN + k], wv.x, a0);
        a0 = fmaf(xs[0 * HIDDEN + k + 1], wv.y, a0);
        a0 = fmaf(xs[0 * HIDDEN + k + 2], wv.z, a0);
        a0 = fmaf(xs[0 * HIDDEN + k + 3], wv.w, a0);
        a1 = fmaf(xs[1 * HIDDEN + k], wv.x, a1);
        a1 = fmaf(xs[1 * HIDDEN + k + 1], wv.y, a1);
        a1 = fmaf(xs[1 * HIDDEN + k + 2], wv.z, a1);
        a1 = fmaf(xs[1 * HIDDEN + k + 3], wv.w, a1);
        a2 = fmaf(xs[2 * HIDDEN + k], wv.x, a2);
        a2 = fmaf(xs[2 * HIDDEN + k + 1], wv.y, a2);
        a2 = fmaf(xs[2 * HIDDEN + k + 2], wv.z, a2);
        a2 = fmaf(xs[2 * HIDDEN + k + 3], wv.w, a2);
        a3 = fmaf(xs[3 * HIDDEN + k], wv.x, a3);
        a3 = fmaf(xs[3 * HIDDEN + k + 1], wv.y, a3);
        a3 = fmaf(xs[3 * HIDDEN + k + 2], wv.z, a3);
        a3 = fmaf(xs[3 * HIDDEN + k + 3], wv.w, a3);
    }
    lgs[0 * NEXPERTS + e] = a0;
    lgs[1 * NEXPERTS + e] = a1;
    lgs[2 * NEXPERTS + e] = a2;
    lgs[3 * NEXPERTS + e] = a3;
    __syncthreads();

    const int wid = e >> 5, lane = e & 31;
    if (wid < ntok) {
        const int tok = g_risky[base + wid];
        float lg[8], bb[8];
#pragma unroll
        for (int j = 0; j < 8; j++) {
            lg[j] = lgs[wid * NEXPERTS + lane * 8 + j];
            bb[j] = bias[lane * 8 + j];
        }
        route_token_warp(lg, bb, lane, tok, T, out);
    }
}

// ---------------------------------------------------------------------------
extern "C" void kernel_launch(void* const* d_in, const int* in_sizes, int n_in,
                              void* d_out, int out_size) {
    const float* x    = (const float*)d_in[0];
    const float* w    = (const float*)d_in[1];
    const float* bias = (const float*)d_in[2];
    float* out = (float*)d_out;

    const int T = in_sizes[0] / HIDDEN;  // 8192

    cudaFuncSetAttribute(gemm_tc_kernel,
                         cudaFuncAttributeMaxDynamicSharedMemorySize, SMEM_TOTAL);
    cudaFuncSetAttribute(fix_kernel,
                         cudaFuncAttributeMaxDynamicSharedMemorySize, FIX_SMEM);

    reset_kernel<<<1, 32>>>();
    presplit_kernel<<<NEXPERTS * HIDDEN / (256 * 8), 256>>>(w);

    dim3 grid(T / 128, 2);
    gemm_tc_kernel<<<grid, 256, SMEM_TOTAL>>>(x, T);

    routing_kernel<<<T / 8, 256>>>(bias, out, T);

    fix_kernel<<<(MAX_T + FIX_TPB - 1) / FIX_TPB, 256, FIX_SMEM>>>(x, w, bias, out, T);
}

// round 16
// speedup vs baseline: 1.0470x; 1.0470x over previous
#include <cuda_runtime.h>
#include <cuda_bf16.h>
#include <cstdint>

#define HIDDEN   7168
#define NEXPERTS 256
#define TOPK     8
#define NGROUP   8
#define TOPKGRP  4
#define SCALING  2.5f

#define MAX_T    8192
#define KT       64
#define NKT      (HIDDEN / KT)      // 112
#define RISKY_TH 4e-5f

// ---------------------------------------------------------------------------
// device scratch
// ---------------------------------------------------------------------------
__device__ float g_logits[MAX_T * NEXPERTS];
__device__ __align__(16) __nv_bfloat16 g_bterm[2][NEXPERTS * HIDDEN];
__device__ int g_risky_count;
__device__ int g_risky[MAX_T];

// ---------------------------------------------------------------------------
// helpers
// ---------------------------------------------------------------------------
__device__ __forceinline__ uint32_t smem_u32(const void* p) {
    uint32_t a;
    asm("{ .reg .u64 t; cvta.to.shared.u64 t, %1; cvt.u32.u64 %0, t; }"
        : "=r"(a) : "l"(p));
    return a;
}
__device__ __forceinline__ uint32_t sw128(uint32_t off) {
    return off ^ ((off >> 3) & 0x70);
}
#define STS128(a, r0, r1, r2, r3) \
    asm volatile("st.shared.v4.b32 [%0], {%1,%2,%3,%4};" :: "r"(a), "r"(r0), "r"(r1), "r"(r2), "r"(r3) : "memory")
#define CP_ASYNC16(dst, src) \
    asm volatile("cp.async.ca.shared.global [%0], [%1], 16;" :: "r"(dst), "l"(src) : "memory")
#define CP_COMMIT() asm volatile("cp.async.commit_group;" ::: "memory")
#define CP_WAIT1()  asm volatile("cp.async.wait_group 1;" ::: "memory")
#define CP_WAIT0()  asm volatile("cp.async.wait_group 0;" ::: "memory")

__device__ __forceinline__ void ldsm4(uint32_t* r, uint32_t addr) {
    asm volatile("ldmatrix.sync.aligned.m8n8.x4.shared.b16 {%0,%1,%2,%3}, [%4];"
        : "=r"(r[0]), "=r"(r[1]), "=r"(r[2]), "=r"(r[3]) : "r"(addr));
}
__device__ __forceinline__ void mma_bf16(float* c, const uint32_t* a,
                                         uint32_t b0, uint32_t b1) {
    asm volatile(
        "mma.sync.aligned.m16n8k16.row.col.f32.bf16.bf16.f32 "
        "{%0,%1,%2,%3}, {%4,%5,%6,%7}, {%8,%9}, {%0,%1,%2,%3};"
        : "+f"(c[0]), "+f"(c[1]), "+f"(c[2]), "+f"(c[3])
        : "r"(a[0]), "r"(a[1]), "r"(a[2]), "r"(a[3]), "r"(b0), "r"(b1));
}

// ---------------------------------------------------------------------------
// fp32 -> 2x bf16 split of 8 consecutive elements -> packed bf16x2 words
// ---------------------------------------------------------------------------
__device__ __forceinline__ uint32_t pk2(float lo, float hi) {
    uint32_t r;
    asm("cvt.rn.bf16x2.f32 %0, %1, %2;" : "=r"(r) : "f"(hi), "f"(lo));
    return r;
}
__device__ __forceinline__ void split8_2(const float* f, uint32_t* p0, uint32_t* p1) {
#pragma unroll
    for (int j = 0; j < 4; j++) {
        float a = f[2 * j], b = f[2 * j + 1];
        uint32_t c0 = pk2(a, b);
        float a0 = __uint_as_float(c0 << 16);
        float b0 = __uint_as_float(c0 & 0xffff0000u);
        uint32_t c1 = pk2(a - a0, b - b0);
        p0[j] = c0; p1[j] = c1;
    }
}

// ---------------------------------------------------------------------------
// small utility kernels
// ---------------------------------------------------------------------------
__global__ void reset_kernel() {
    if (threadIdx.x == 0) g_risky_count = 0;
}

__global__ void __launch_bounds__(256)
presplit_kernel(const float* __restrict__ W) {
    size_t i = ((size_t)blockIdx.x * 256 + threadIdx.x) * 8;
    const float4* s = reinterpret_cast<const float4*>(W + i);
    float4 f0 = s[0], f1 = s[1];
    float f[8] = {f0.x, f0.y, f0.z, f0.w, f1.x, f1.y, f1.z, f1.w};
    uint32_t p0[4], p1[4];
    split8_2(f, p0, p1);
    *reinterpret_cast<uint4*>(&g_bterm[0][i]) = make_uint4(p0[0], p0[1], p0[2], p0[3]);
    *reinterpret_cast<uint4*>(&g_bterm[1][i]) = make_uint4(p1[0], p1[1], p1[2], p1[3]);
}

// ---------------------------------------------------------------------------
// GEMM: logits = x @ W^T, 3-product 2-term bf16 emulation on mma.sync.
// CTA tile 64x128, 128 threads (4 warps of 32x64), occupancy 2, 96KB smem.
// grid (T/64, 2) = 256 CTAs.
// ---------------------------------------------------------------------------
#define A_TERM_BYTES 8192           // 64 rows x 64 bf16 x 2B
#define B_TERM_BYTES 16384          // 128 rows x 64 bf16 x 2B
#define SMEM_A(buf, t) ((uint32_t)((buf) * 2 + (t)) * A_TERM_BYTES)
#define SMEM_B(buf, t) ((uint32_t)(32768 + ((buf) * 2 + (t)) * B_TERM_BYTES))
#define SMEM_TOTAL     98304

__global__ void __launch_bounds__(128, 2)
gemm_tc_kernel(const float* __restrict__ A, int T) {
    extern __shared__ char smem[];
    const uint32_t sb = smem_u32(smem);
    const int tid = threadIdx.x, wid = tid >> 5, lane = tid & 31;
    const int rowBase = blockIdx.x * 64;
    const int colBase = blockIdx.y * 128;
    const int warpM = (wid & 1) * 32;
    const int warpN = (wid >> 1) * 64;

    const float* Abase = A + (size_t)rowBase * HIDDEN;
    const int ldKc = (tid & 7) * 8;   // col offset (elements) within 64-wide tile

    float acc[2][8][4];
#pragma unroll
    for (int mt = 0; mt < 2; mt++)
#pragma unroll
        for (int nf = 0; nf < 8; nf++)
#pragma unroll
            for (int j = 0; j < 4; j++) acc[mt][nf][j] = 0.0f;

    // ---- prologue: A(0) regs (4 chunks) + B(0) cp.async (8 chunks x 2 terms) ----
    float4 aReg[8];
#pragma unroll
    for (int i = 0; i < 4; i++) {
        const int row = (tid + i * 128) >> 3;          // 0..63
        const float* src = Abase + (size_t)row * HIDDEN + ldKc;
        aReg[2 * i]     = *reinterpret_cast<const float4*>(src);
        aReg[2 * i + 1] = *reinterpret_cast<const float4*>(src + 4);
    }
#pragma unroll
    for (int t = 0; t < 2; t++)
#pragma unroll
        for (int i = 0; i < 8; i++) {
            const int row = (tid + i * 128) >> 3;      // 0..127
            const __nv_bfloat16* src =
                &g_bterm[t][(size_t)(colBase + row) * HIDDEN + ldKc];
            CP_ASYNC16(sb + SMEM_B(0, t) + sw128((uint32_t)(row * 128 + ldKc * 2)),
                       src);
        }
    CP_COMMIT();

    for (int kt = 0; kt < NKT; kt++) {
        const int buf = kt & 1;

        __syncthreads();  // previous compute done; buffers free

        // ---- STS A(kt): split fp32 regs into 2 bf16 term tiles ----
#pragma unroll
        for (int i = 0; i < 4; i++) {
            const int row = (tid + i * 128) >> 3;
            float f[8] = {aReg[2 * i].x, aReg[2 * i].y, aReg[2 * i].z, aReg[2 * i].w,
                          aReg[2 * i + 1].x, aReg[2 * i + 1].y,
                          aReg[2 * i + 1].z, aReg[2 * i + 1].w};
            uint32_t p0[4], p1[4];
            split8_2(f, p0, p1);
            const uint32_t sw = sw128((uint32_t)(row * 128 + ldKc * 2));
            STS128(sb + SMEM_A(buf, 0) + sw, p0[0], p0[1], p0[2], p0[3]);
            STS128(sb + SMEM_A(buf, 1) + sw, p1[0], p1[1], p1[2], p1[3]);
        }

        // ---- prefetch tile kt+1 ----
        if (kt + 1 < NKT) {
            const int nbuf = buf ^ 1;
            const int koff = (kt + 1) * KT;
#pragma unroll
            for (int t = 0; t < 2; t++)
#pragma unroll
                for (int i = 0; i < 8; i++) {
                    const int row = (tid + i * 128) >> 3;
                    const __nv_bfloat16* src =
                        &g_bterm[t][(size_t)(colBase + row) * HIDDEN + koff + ldKc];
                    CP_ASYNC16(sb + SMEM_B(nbuf, t) +
                                   sw128((uint32_t)(row * 128 + ldKc * 2)),
                               src);
                }
            CP_COMMIT();
#pragma unroll
            for (int i = 0; i < 4; i++) {
                const int row = (tid + i * 128) >> 3;
                const float* src = Abase + (size_t)row * HIDDEN + koff + ldKc;
                aReg[2 * i]     = *reinterpret_cast<const float4*>(src);
                aReg[2 * i + 1] = *reinterpret_cast<const float4*>(src + 4);
            }
            CP_WAIT1();  // B(kt) complete
        } else {
            CP_WAIT0();
        }
        __syncthreads();

        // ---- compute tile kt: 4 k-steps x 3 term-products ----
#pragma unroll
        for (int ks = 0; ks < 4; ks++) {
            const uint32_t colb = (uint32_t)(ks * 32 + (lane >> 4) * 16);

            uint32_t afr[2][2][4];
#pragma unroll
            for (int t = 0; t < 2; t++)
#pragma unroll
                for (int mt = 0; mt < 2; mt++) {
                    const uint32_t row = (uint32_t)(warpM + mt * 16 + (lane & 15));
                    ldsm4(afr[t][mt], sb + SMEM_A(buf, t) + sw128(row * 128 + colb));
                }

#pragma unroll
            for (int tb = 0; tb < 2; tb++) {
                uint32_t bfr[4][4];
#pragma unroll
                for (int nr = 0; nr < 4; nr++) {
                    const uint32_t row = (uint32_t)(warpN + nr * 16 + (lane & 15));
                    ldsm4(bfr[nr], sb + SMEM_B(buf, tb) + sw128(row * 128 + colb));
                }
                const int numA = 2 - tb;  // (0,0),(1,0),(0,1): skip (1,1)
#pragma unroll
                for (int ta = 0; ta < 2; ta++) {
                    if (ta > numA - 1) break;
#pragma unroll
                    for (int mt = 0; mt < 2; mt++)
#pragma unroll
                        for (int nr = 0; nr < 4; nr++) {
                            mma_bf16(acc[mt][nr * 2],     afr[ta][mt], bfr[nr][0], bfr[nr][2]);
                            mma_bf16(acc[mt][nr * 2 + 1], afr[ta][mt], bfr[nr][1], bfr[nr][3]);
                        }
                }
            }
        }
    }

    // ---- epilogue ----
#pragma unroll
    for (int mt = 0; mt < 2; mt++) {
        const int r0 = rowBase + warpM + mt * 16 + (lane >> 2);
#pragma unroll
        for (int nf = 0; nf < 8; nf++) {
            const int col = colBase + warpN + nf * 8 + (lane & 3) * 2;
            *reinterpret_cast<float2*>(g_logits + (size_t)r0 * NEXPERTS + col) =
                make_float2(acc[mt][nf][0], acc[mt][nf][1]);
            *reinterpret_cast<float2*>(g_logits + (size_t)(r0 + 8) * NEXPERTS + col) =
                make_float2(acc[mt][nf][2], acc[mt][nf][3]);
        }
    }
}

// ---------------------------------------------------------------------------
// warp-collective routing for one token; returns min decision margin.
// ---------------------------------------------------------------------------
__device__ __forceinline__ float route_token_warp(const float* lg, const float* bb,
                                                  int lane, int token, int T,
                                                  float* out) {
    const float NEG_INF = __int_as_float(0xff800000);

    float s[8], sc[8];
#pragma unroll
    for (int j = 0; j < 8; j++) {
        s[j]  = 1.0f / (1.0f + expf(-lg[j]));
        sc[j] = s[j] + bb[j];
    }

    float m1 = NEG_INF, m2 = NEG_INF;
#pragma unroll
    for (int j = 0; j < 8; j++) {
        float v = sc[j];
        if (v > m1) { m2 = m1; m1 = v; }
        else if (v > m2) { m2 = v; }
    }
#pragma unroll
    for (int off = 1; off <= 2; off <<= 1) {
        float om1 = __shfl_xor_sync(0xffffffffu, m1, off);
        float om2 = __shfl_xor_sync(0xffffffffu, m2, off);
        float n1 = fmaxf(m1, om1);
        float n2 = fmaxf(fminf(m1, om1), fmaxf(m2, om2));
        m1 = n1; m2 = n2;
    }
    const float gscore = m1 + m2;

    float gs[8];
#pragma unroll
    for (int g = 0; g < 8; g++)
        gs[g] = __shfl_sync(0xffffffffu, gscore, g * 4);

    float val4 = 1e30f, val5 = -1e30f;
    int myrank = 0;
#pragma unroll
    for (int g = 0; g < 8; g++) {
        int rank = 0;
#pragma unroll
        for (int h = 0; h < 8; h++)
            rank += (gs[h] > gs[g]) || (gs[h] == gs[g] && h < g);
        if (rank < TOPKGRP) val4 = fminf(val4, gs[g]);
        else                val5 = fmaxf(val5, gs[g]);
        if (g == (lane >> 2)) myrank = rank;
    }
    float margin = val4 - val5;
    const bool sel = (myrank < TOPKGRP);

    float msc[8];
#pragma unroll
    for (int j = 0; j < 8; j++) msc[j] = sel ? sc[j] : 0.0f;

    float wv[TOPK];
    int   wi[TOPK];
    float sum_s = 0.0f;
    float prev_bv = 0.0f;

#pragma unroll
    for (int it = 0; it <= TOPK; it++) {
        float bv = msc[0];
        int   bj = 0;
#pragma unroll
        for (int j = 1; j < 8; j++)
            if (msc[j] > bv) { bv = msc[j]; bj = j; }
        int   bidx = lane * 8 + bj;
        float bs   = s[bj];

#pragma unroll
        for (int off = 16; off >= 1; off >>= 1) {
            float ov = __shfl_xor_sync(0xffffffffu, bv, off);
            int   oi = __shfl_xor_sync(0xffffffffu, bidx, off);
            float os = __shfl_xor_sync(0xffffffffu, bs, off);
            if (ov > bv || (ov == bv && oi < bidx)) { bv = ov; bidx = oi; bs = os; }
        }
        if (it > 0) margin = fminf(margin, prev_bv - bv);
        prev_bv = bv;

        if (it < TOPK) {
            wv[it] = bs;
            wi[it] = bidx;
            sum_s += bs;
            if ((bidx >> 3) == lane) msc[bidx & 7] = NEG_INF;
        }
    }

    if (lane == 0) {
        const float inv = SCALING / (sum_s + 1e-20f);
        float* oidx = out + (size_t)token * TOPK;
        float* ow   = out + (size_t)T * TOPK + (size_t)token * TOPK;
#pragma unroll
        for (int it = 0; it < TOPK; it++) {
            oidx[it] = (float)wi[it];
            ow[it]   = wv[it] * inv;
        }
    }
    return margin;
}

// ---------------------------------------------------------------------------
// Routing: one warp per token; flags risky (small-margin) tokens.
// ---------------------------------------------------------------------------
__global__ void __launch_bounds__(256)
routing_kernel(const float* __restrict__ bias, float* __restrict__ out, int T) {
    const int warp = (blockIdx.x * blockDim.x + threadIdx.x) >> 5;
    const int lane = threadIdx.x & 31;
    if (warp >= T) return;

    const float* lrow = g_logits + (size_t)warp * NEXPERTS;
    float4 l0 = *reinterpret_cast<const float4*>(lrow + lane * 8);
    float4 l1 = *reinterpret_cast<const float4*>(lrow + lane * 8 + 4);
    float4 b0 = *reinterpret_cast<const float4*>(bias + lane * 8);
    float4 b1 = *reinterpret_cast<const float4*>(bias + lane * 8 + 4);
    float lg[8] = {l0.x, l0.y, l0.z, l0.w, l1.x, l1.y, l1.z, l1.w};
    float bb[8] = {b0.x, b0.y, b0.z, b0.w, b1.x, b1.y, b1.z, b1.w};

    float mm = route_token_warp(lg, bb, lane, warp, T, out);

    if (lane == 0 && mm < RISKY_TH) {
        int slot = atomicAdd(&g_risky_count, 1);
        g_risky[slot] = warp;
    }
}

// ---------------------------------------------------------------------------
// Exact fix: recompute risky tokens' logits with sequential fp32 FMA.
// 16 tokens/block; x staged in K-chunks so W is read once per 16 tokens.
// ---------------------------------------------------------------------------
#define FIX_TPB   16
#define FIX_CHUNK 1792                               // K chunk (HIDDEN/4)
#define FIX_SMEM  ((FIX_TPB * FIX_CHUNK + FIX_TPB * NEXPERTS) * 4)  // 128KB

__global__ void __launch_bounds__(256)
fix_kernel(const float* __restrict__ x, const float* __restrict__ w,
           const float* __restrict__ bias, float* __restrict__ out, int T) {
    const int cnt = g_risky_count;
    const int base = blockIdx.x * FIX_TPB;
    if (base >= cnt) return;
    const int ntok = min(FIX_TPB, cnt - base);

    extern __shared__ float fsm[];
    float* xs  = fsm;                                // [FIX_TPB][FIX_CHUNK]
    float* lgs = fsm + FIX_TPB * FIX_CHUNK;          // [FIX_TPB][NEXPERTS]

    const int e = threadIdx.x;                       // expert id
    const float* wr = w + (size_t)e * HIDDEN;

    float accs[FIX_TPB];
#pragma unroll
    for (int j = 0; j < FIX_TPB; j++) accs[j] = 0.0f;

    for (int c = 0; c < HIDDEN / FIX_CHUNK; c++) {
        __syncthreads();  // previous chunk's reads done
        for (int j = 0; j < ntok; j++) {
            const int tok = g_risky[base + j];
            const float4* src = reinterpret_cast<const float4*>(
                x + (size_t)tok * HIDDEN + c * FIX_CHUNK);
            float4* dst = reinterpret_cast<float4*>(xs + j * FIX_CHUNK);
            for (int i = threadIdx.x; i < FIX_CHUNK / 4; i += 256) dst[i] = src[i];
        }
        __syncthreads();

        const float4* wc = reinterpret_cast<const float4*>(wr + c * FIX_CHUNK);
        for (int k4 = 0; k4 < FIX_CHUNK / 4; k4++) {
            const float4 wv = wc[k4];
            const int k = k4 * 4;
#pragma unroll
            for (int j = 0; j < FIX_TPB; j++) {
                const float* xr = xs + j * FIX_CHUNK + k;
                float a = accs[j];
                a = fmaf(xr[0], wv.x, a);
                a = fmaf(xr[1], wv.y, a);
                a = fmaf(xr[2], wv.z, a);
                a = fmaf(xr[3], wv.w, a);
                accs[j] = a;
            }
        }
    }

#pragma unroll
    for (int j = 0; j < FIX_TPB; j++)
        lgs[j * NEXPERTS + e] = accs[j];
    __syncthreads();

    const int wid = e >> 5, lane = e & 31;
    float bb[8];
#pragma unroll
    for (int j = 0; j < 8; j++) bb[j] = bias[lane * 8 + j];

    for (int p = 0; p < FIX_TPB; p += 8) {
        const int j = p + wid;
        if (j < ntok) {
            const int tok = g_risky[base + j];
            float lg[8];
#pragma unroll
            for (int q = 0; q < 8; q++)
                lg[q] = lgs[j * NEXPERTS + lane * 8 + q];
            route_token_warp(lg, bb, lane, tok, T, out);
        }
    }
}

// ---------------------------------------------------------------------------
extern "C" void kernel_launch(void* const* d_in, const int* in_sizes, int n_in,
                              void* d_out, int out_size) {
    const float* x    = (const float*)d_in[0];
    const float* w    = (const float*)d_in[1];
    const float* bias = (const float*)d_in[2];
    float* out = (float*)d_out;

    const int T = in_sizes[0] / HIDDEN;  // 8192

    cudaFuncSetAttribute(gemm_tc_kernel,
                         cudaFuncAttributeMaxDynamicSharedMemorySize, SMEM_TOTAL);
    cudaFuncSetAttribute(fix_kernel,
                         cudaFuncAttributeMaxDynamicSharedMemorySize, FIX_SMEM);

    reset_kernel<<<1, 32>>>();
    presplit_kernel<<<NEXPERTS * HIDDEN / (256 * 8), 256>>>(w);

    dim3 grid(T / 64, 2);
    gemm_tc_kernel<<<grid, 128, SMEM_TOTAL>>>(x, T);

    routing_kernel<<<T / 8, 256>>>(bias, out, T);

    fix_kernel<<<(MAX_T + FIX_TPB - 1) / FIX_TPB, 256, FIX_SMEM>>>(x, w, bias, out, T);
}